// round 13
// baseline (speedup 1.0000x reference)
#include <cuda_runtime.h>
#include <cuda_bf16.h>
#include <cstdint>

// Problem constants
#define RNN_B     32
#define RNN_T     256
#define RNN_H     512
#define RNN_V     32000
#define TB_ROWS   (RNN_T * RNN_B)       // 8192

// -------------------- device scratch (no allocation allowed) ----------------
__device__ float        g_Hs[TB_ROWS * RNN_H];   // all hidden states, 16 MB
__device__ int          g_x_is_i32;              // 1 if tokens stored as int32
__device__ unsigned int g_bar;                   // grid barrier counter

// -------------------- packed f32x2 helpers (GEMM only) ----------------------
#define FMA2(accv, av, bv) \
    asm("fma.rn.f32x2 %0, %1, %2, %0;" : "+l"(accv) : "l"(av), "l"(bv))

__device__ __forceinline__ unsigned long long dup_f32(float x) {
    unsigned long long r;
    asm("mov.b64 %0, {%1, %1};" : "=l"(r) : "f"(x));
    return r;
}
__device__ __forceinline__ float2 u64_as_f2(unsigned long long v) {
    float2 r;
    asm("mov.b64 {%0, %1}, %2;" : "=f"(r.x), "=f"(r.y) : "l"(v));
    return r;
}

// =============================================================================
// MATCHED reference arithmetic (decoded via R9-R11 probes):
//   dot  = split-K=2: chain(k 0..255) then chain(k 256..511), p0+p1
//   tanh = XLA fast-tanh, FMA Horner, clamp +/-7.99881172180175781
//   arg  = (e + dot) + b_h
// All via explicit RN intrinsics / fmaf: immune to -fmad rewrites.
// =============================================================================
__device__ __forceinline__ float xla_tanh_t2(float a) {
    const float kClamp = 7.99881172180175781f;
    float x = fminf(fmaxf(a, -kClamp), kClamp);
    float x2 = __fmul_rn(x, x);
    float p = -2.76076847742355e-16f;
    p = fmaf(x2, p,  2.00018790482477e-13f);
    p = fmaf(x2, p, -8.60467152213735e-11f);
    p = fmaf(x2, p,  5.12229709037114e-08f);
    p = fmaf(x2, p,  1.48572235717979e-05f);
    p = fmaf(x2, p,  6.37261928875436e-04f);
    p = fmaf(x2, p,  4.89352455891786e-03f);
    p = __fmul_rn(x, p);
    float q = 1.19825839466702e-06f;
    q = fmaf(x2, q,  1.18534705686654e-04f);
    q = fmaf(x2, q,  2.26843463243900e-03f);
    q = fmaf(x2, q,  4.89352518554385e-03f);
    float r = __fdiv_rn(p, q);
    return (fabsf(a) < 0.0004f) ? a : r;
}

__device__ __forceinline__ float chain_seq(const float* __restrict__ h,
                                           const float* __restrict__ w,
                                           int k0, int k1) {
    float acc = 0.f;
    #pragma unroll 8
    for (int k = k0; k < k1; ++k) acc = fmaf(h[k], w[k], acc);
    return acc;
}

// =============================================================================
// Kernel 0: probe token dtype (int32 vs int64) and reset grid barrier.
// =============================================================================
__global__ void __launch_bounds__(256, 1)
rnn_prep(const unsigned int* __restrict__ xw) {
    __shared__ int s_any;
    if (threadIdx.x == 0) s_any = 0;
    __syncthreads();
    int any = 0;
    for (int i = threadIdx.x; i < (RNN_B * RNN_T) / 2; i += 256)
        any |= (xw[2 * i + 1] != 0u);
    if (any) atomicOr(&s_any, 1);
    __syncthreads();
    if (threadIdx.x == 0) { g_x_is_i32 = s_any; g_bar = 0u; }
}

// =============================================================================
// Kernel 1: sequential recurrence, bit-exact matched arithmetic (S2 x T2).
// 64 CTAs x 256 threads, software grid barrier per step. Thread (b=tid>>3,
// c=tid&7) computes H_t[b][cg].
// =============================================================================
__global__ void __launch_bounds__(256, 1)
rnn_recurrence(const void*  __restrict__ xraw,
               const float* __restrict__ H0,
               const float* __restrict__ W_xh,
               const float* __restrict__ W_hh,
               const float* __restrict__ b_h) {
    __shared__ float Wsm[8 * 516];    // W_hh[:, cg] slices, padded stride
    __shared__ float Hsm[32 * 516];   // H_prev staged per step, padded stride

    const int tid = threadIdx.x;
    const int b   = tid >> 3;                      // batch row 0..31
    const int c   = tid & 7;                       // local column 0..7
    const int cg  = blockIdx.x * 8 + c;            // global H column

    for (int i = tid; i < 8 * 512; i += 256) {
        int jc = i >> 9, k = i & 511;
        Wsm[jc * 516 + k] = W_hh[(size_t)k * RNN_H + blockIdx.x * 8 + jc];
    }
    const float bh = b_h[cg];
    __syncthreads();

    const int        is32 = g_x_is_i32;
    const int*       x32  = (const int*)xraw;
    const long long* x64  = (const long long*)xraw;
    const float*     wrow = Wsm + c * 516;
    const float*     hrow = Hsm + b * 516;
    const unsigned   G    = gridDim.x;

    for (int t = 0; t < RNN_T; ++t) {
        // ---- cooperative stage of H_prev (32x512) into SMEM ----
        const float* Hp = (t == 0) ? H0
                                   : (g_Hs + (size_t)(t - 1) * (RNN_B * RNN_H));
        for (int j = tid; j < (RNN_B * RNN_H) / 4; j += 256) {
            int br = j >> 7, k4 = j & 127;
            float4 v = __ldcg((const float4*)(Hp + (size_t)br * RNN_H + k4 * 4));
            *(float4*)(Hsm + br * 516 + k4 * 4) = v;
        }
        __syncthreads();

        // ---- matched dot: split-K=2, sequential chains, p0 + p1 ----
        float p0  = chain_seq(hrow, wrow, 0,   256);
        float p1  = chain_seq(hrow, wrow, 256, 512);
        float acc = __fadd_rn(p0, p1);

        long long tok = is32 ? (long long)x32[b * RNN_T + t] : x64[b * RNN_T + t];
        float e   = W_xh[(size_t)tok * RNN_H + cg];
        float arg = __fadd_rn(__fadd_rn(e, acc), bh);
        float h   = xla_tanh_t2(arg);

        __stcg(g_Hs + (size_t)t * (RNN_B * RNN_H) + b * RNN_H + cg, h);

        // -------- software grid barrier (monotonic counter) --------
        __threadfence();
        __syncthreads();
        if (tid == 0) {
            atomicAdd(&g_bar, 1u);
            const unsigned target = (unsigned)(t + 1) * G;
            while (*((volatile unsigned int*)&g_bar) < target) __nanosleep(64);
            __threadfence();
        }
        __syncthreads();
    }
}

// =============================================================================
// Kernel 2: out[8192,32000] = g_Hs[8192,512] @ W_hy[512,32000] + b_y
// fp32 SIMT GEMM with packed fma.rn.f32x2 (2x FFMA throughput on sm_103a).
// 128x128 CTA tile, BK=16, 256 threads, 8x8 microtile (8 M x 4 packed pairs),
// double-buffered SMEM, one __syncthreads per K-tile.
// =============================================================================
#define GBM 128
#define GBN 128
#define GBK 16

__global__ void __launch_bounds__(256, 1)
rnn_out_gemm(const float* __restrict__ Why,
             const float* __restrict__ b_y,
             float*       __restrict__ out) {
    __shared__ __align__(16) float As[2][GBK][GBM + 4];
    __shared__ __align__(16) float Bs[2][GBK][GBN];

    const int tid = threadIdx.x;
    const int tx  = tid & 15;               // N micro index
    const int ty  = tid >> 4;               // M micro index
    const int n0  = blockIdx.x * GBN;
    const int m0  = blockIdx.y * GBM;
    const float* A = g_Hs;                  // [8192][512] row-major

    const int ar  = tid >> 2;               // A rows: ar, ar+64
    const int akq = tid & 3;                // A float4 within 16-wide k
    const int bkr = tid >> 5;               // B rows: bkr, bkr+8
    const int bnc = tid & 31;               // B float4 within 128-wide n

    unsigned long long acc[8][4];
    #pragma unroll
    for (int m = 0; m < 8; ++m)
        #pragma unroll
        for (int p = 0; p < 4; ++p) acc[m][p] = 0ull;

    // prologue: K-tile 0 into buffer 0
    {
        float4 a0 = *(const float4*)(A + (size_t)(m0 + ar) * RNN_H + akq * 4);
        float4 a1 = *(const float4*)(A + (size_t)(m0 + ar + 64) * RNN_H + akq * 4);
        float4 bb0 = *(const float4*)(Why + (size_t)bkr * RNN_V + n0 + bnc * 4);
        float4 bb1 = *(const float4*)(Why + (size_t)(bkr + 8) * RNN_V + n0 + bnc * 4);
        As[0][akq * 4 + 0][ar] = a0.x; As[0][akq * 4 + 1][ar] = a0.y;
        As[0][akq * 4 + 2][ar] = a0.z; As[0][akq * 4 + 3][ar] = a0.w;
        As[0][akq * 4 + 0][ar + 64] = a1.x; As[0][akq * 4 + 1][ar + 64] = a1.y;
        As[0][akq * 4 + 2][ar + 64] = a1.z; As[0][akq * 4 + 3][ar + 64] = a1.w;
        *(float4*)&Bs[0][bkr][bnc * 4]     = bb0;
        *(float4*)&Bs[0][bkr + 8][bnc * 4] = bb1;
    }
    __syncthreads();

    const int NKT = RNN_H / GBK;            // 32
    for (int kt = 0; kt < NKT; ++kt) {
        const int cur = kt & 1;
        float4 na0, na1, nb0, nb1;
        if (kt < NKT - 1) {
            const int kb = (kt + 1) * GBK;
            na0 = *(const float4*)(A + (size_t)(m0 + ar) * RNN_H + kb + akq * 4);
            na1 = *(const float4*)(A + (size_t)(m0 + ar + 64) * RNN_H + kb + akq * 4);
            nb0 = *(const float4*)(Why + (size_t)(kb + bkr) * RNN_V + n0 + bnc * 4);
            nb1 = *(const float4*)(Why + (size_t)(kb + bkr + 8) * RNN_V + n0 + bnc * 4);
        }

        #pragma unroll
        for (int kk = 0; kk < GBK; ++kk) {
            float4 af0 = *(const float4*)&As[cur][kk][ty * 8];
            float4 af1 = *(const float4*)&As[cur][kk][ty * 8 + 4];
            ulonglong2 bb0 = *(const ulonglong2*)&Bs[cur][kk][tx * 8];
            ulonglong2 bb1 = *(const ulonglong2*)&Bs[cur][kk][tx * 8 + 4];
            float av[8] = {af0.x, af0.y, af0.z, af0.w, af1.x, af1.y, af1.z, af1.w};
            #pragma unroll
            for (int m = 0; m < 8; ++m) {
                unsigned long long aa = dup_f32(av[m]);
                FMA2(acc[m][0], aa, bb0.x);
                FMA2(acc[m][1], aa, bb0.y);
                FMA2(acc[m][2], aa, bb1.x);
                FMA2(acc[m][3], aa, bb1.y);
            }
        }

        if (kt < NKT - 1) {
            const int nxt = cur ^ 1;
            As[nxt][akq * 4 + 0][ar] = na0.x; As[nxt][akq * 4 + 1][ar] = na0.y;
            As[nxt][akq * 4 + 2][ar] = na0.z; As[nxt][akq * 4 + 3][ar] = na0.w;
            As[nxt][akq * 4 + 0][ar + 64] = na1.x; As[nxt][akq * 4 + 1][ar + 64] = na1.y;
            As[nxt][akq * 4 + 2][ar + 64] = na1.z; As[nxt][akq * 4 + 3][ar + 64] = na1.w;
            *(float4*)&Bs[nxt][bkr][bnc * 4]     = nb0;
            *(float4*)&Bs[nxt][bkr + 8][bnc * 4] = nb1;
            __syncthreads();
        }
    }

    // epilogue: add bias, store
    float bv[8];
    #pragma unroll
    for (int j = 0; j < 8; ++j) bv[j] = b_y[n0 + tx * 8 + j];
    #pragma unroll
    for (int m = 0; m < 8; ++m) {
        float2 c0 = u64_as_f2(acc[m][0]);
        float2 c1 = u64_as_f2(acc[m][1]);
        float2 c2 = u64_as_f2(acc[m][2]);
        float2 c3 = u64_as_f2(acc[m][3]);
        float4 v0 = make_float4(c0.x + bv[0], c0.y + bv[1], c1.x + bv[2], c1.y + bv[3]);
        float4 v1 = make_float4(c2.x + bv[4], c2.y + bv[5], c3.x + bv[6], c3.y + bv[7]);
        float* op = out + (size_t)(m0 + ty * 8 + m) * RNN_V + n0 + tx * 8;
        *(float4*)op       = v0;
        *(float4*)(op + 4) = v1;
    }
}

// =============================================================================
// Kernel 3: optional H_final tail
// =============================================================================
__global__ void rnn_copy_hfinal(float* __restrict__ dst) {
    int i = blockIdx.x * 256 + threadIdx.x;
    if (i < RNN_B * RNN_H)
        dst[i] = g_Hs[(size_t)(RNN_T - 1) * (RNN_B * RNN_H) + i];
}

// =============================================================================
// launch
// =============================================================================
extern "C" void kernel_launch(void* const* d_in, const int* in_sizes, int n_in,
                              void* d_out, int out_size) {
    int ix = 0, ih0 = 1, iwxh = 2, iwhh = 3, ibh = 4, iwhy = 5, iby = 6;

    if (n_in == 7) {
        int fx = -1, fh0 = -1, fwhh = -1, fbh = -1, fby = -1, big0 = -1, big1 = -1;
        for (int i = 0; i < 7; ++i) {
            int s = in_sizes[i];
            if      (s == 8192)       fx = i;
            else if (s == 16384)      fh0 = i;
            else if (s == 262144)     fwhh = i;
            else if (s == 512)        fbh = i;
            else if (s == 32000)      fby = i;
            else if (s == 16384000) { if (big0 < 0) big0 = i; else big1 = i; }
        }
        if (fx >= 0 && fh0 >= 0 && fwhh >= 0 && fbh >= 0 && fby >= 0 &&
            big0 >= 0 && big1 >= 0) {
            ix = fx; ih0 = fh0; iwhh = fwhh; ibh = fbh; iby = fby;
            if (fx == 0) { iwxh = big0; iwhy = big1; }
            else         { iwhy = big0; iwxh = big1; }
        }
    }

    const void*  x    = d_in[ix];
    const float* H0   = (const float*)d_in[ih0];
    const float* W_xh = (const float*)d_in[iwxh];
    const float* W_hh = (const float*)d_in[iwhh];
    const float* b_h  = (const float*)d_in[ibh];
    const float* W_hy = (const float*)d_in[iwhy];
    const float* b_y  = (const float*)d_in[iby];
    float* out = (float*)d_out;

    rnn_prep<<<1, 256>>>((const unsigned int*)x);
    rnn_recurrence<<<64, 256>>>(x, H0, W_xh, W_hh, b_h);

    dim3 grid(RNN_V / GBN, TB_ROWS / GBM);   // (250, 64)
    rnn_out_gemm<<<grid, 256>>>(W_hy, b_y, out);

    const long long main_elems = (long long)TB_ROWS * RNN_V;
    if ((long long)out_size >= main_elems + (long long)RNN_B * RNN_H)
        rnn_copy_hfinal<<<(RNN_B * RNN_H + 255) / 256, 256>>>(out + main_elems);
}

// round 14
// speedup vs baseline: 1.6628x; 1.6628x over previous
#include <cuda_runtime.h>
#include <cuda_bf16.h>
#include <cstdint>

// Problem constants
#define RNN_B     32
#define RNN_T     256
#define RNN_H     512
#define RNN_V     32000
#define TB_ROWS   (RNN_T * RNN_B)       // 8192

// -------------------- device scratch (no allocation allowed) ----------------
__device__ float          g_Hs[TB_ROWS * RNN_H];     // hidden states, 16 MB
__device__ int            g_x_is_i32;
__device__ unsigned int   g_bar;
// bf16 split operands for the tensor-core out-GEMM
__device__ __nv_bfloat16  g_Ahi[TB_ROWS * RNN_H];    // 8.4 MB
__device__ __nv_bfloat16  g_Alo[TB_ROWS * RNN_H];
__device__ __nv_bfloat16  g_Bhi[RNN_H * RNN_V];      // 32.8 MB
__device__ __nv_bfloat16  g_Blo[RNN_H * RNN_V];

// =============================================================================
// MATCHED reference arithmetic (decoded R9-R11): split-K=2 fmaf chains + T2 tanh
// =============================================================================
__device__ __forceinline__ float xla_tanh_t2(float a) {
    const float kClamp = 7.99881172180175781f;
    float x = fminf(fmaxf(a, -kClamp), kClamp);
    float x2 = __fmul_rn(x, x);
    float p = -2.76076847742355e-16f;
    p = fmaf(x2, p,  2.00018790482477e-13f);
    p = fmaf(x2, p, -8.60467152213735e-11f);
    p = fmaf(x2, p,  5.12229709037114e-08f);
    p = fmaf(x2, p,  1.48572235717979e-05f);
    p = fmaf(x2, p,  6.37261928875436e-04f);
    p = fmaf(x2, p,  4.89352455891786e-03f);
    p = __fmul_rn(x, p);
    float q = 1.19825839466702e-06f;
    q = fmaf(x2, q,  1.18534705686654e-04f);
    q = fmaf(x2, q,  2.26843463243900e-03f);
    q = fmaf(x2, q,  4.89352518554385e-03f);
    float r = __fdiv_rn(p, q);
    return (fabsf(a) < 0.0004f) ? a : r;
}

__device__ __forceinline__ float chain_seq(const float* __restrict__ h,
                                           const float* __restrict__ w,
                                           int k0, int k1) {
    float acc = 0.f;
    #pragma unroll 8
    for (int k = k0; k < k1; ++k) acc = fmaf(h[k], w[k], acc);
    return acc;
}

// =============================================================================
// Kernel 0: probe token dtype and reset grid barrier.
// =============================================================================
__global__ void __launch_bounds__(256, 1)
rnn_prep(const unsigned int* __restrict__ xw) {
    __shared__ int s_any;
    if (threadIdx.x == 0) s_any = 0;
    __syncthreads();
    int any = 0;
    for (int i = threadIdx.x; i < (RNN_B * RNN_T) / 2; i += 256)
        any |= (xw[2 * i + 1] != 0u);
    if (any) atomicOr(&s_any, 1);
    __syncthreads();
    if (threadIdx.x == 0) { g_x_is_i32 = s_any; g_bar = 0u; }
}

// =============================================================================
// Kernel 1: recurrence, bit-exact matched arithmetic (UNCHANGED from R13 pass)
// =============================================================================
__global__ void __launch_bounds__(256, 1)
rnn_recurrence(const void*  __restrict__ xraw,
               const float* __restrict__ H0,
               const float* __restrict__ W_xh,
               const float* __restrict__ W_hh,
               const float* __restrict__ b_h) {
    __shared__ float Wsm[8 * 516];
    __shared__ float Hsm[32 * 516];

    const int tid = threadIdx.x;
    const int b   = tid >> 3;
    const int c   = tid & 7;
    const int cg  = blockIdx.x * 8 + c;

    for (int i = tid; i < 8 * 512; i += 256) {
        int jc = i >> 9, k = i & 511;
        Wsm[jc * 516 + k] = W_hh[(size_t)k * RNN_H + blockIdx.x * 8 + jc];
    }
    const float bh = b_h[cg];
    __syncthreads();

    const int        is32 = g_x_is_i32;
    const int*       x32  = (const int*)xraw;
    const long long* x64  = (const long long*)xraw;
    const float*     wrow = Wsm + c * 516;
    const float*     hrow = Hsm + b * 516;
    const unsigned   G    = gridDim.x;

    for (int t = 0; t < RNN_T; ++t) {
        const float* Hp = (t == 0) ? H0
                                   : (g_Hs + (size_t)(t - 1) * (RNN_B * RNN_H));
        for (int j = tid; j < (RNN_B * RNN_H) / 4; j += 256) {
            int br = j >> 7, k4 = j & 127;
            float4 v = __ldcg((const float4*)(Hp + (size_t)br * RNN_H + k4 * 4));
            *(float4*)(Hsm + br * 516 + k4 * 4) = v;
        }
        __syncthreads();

        float p0  = chain_seq(hrow, wrow, 0,   256);
        float p1  = chain_seq(hrow, wrow, 256, 512);
        float acc = __fadd_rn(p0, p1);

        long long tok = is32 ? (long long)x32[b * RNN_T + t] : x64[b * RNN_T + t];
        float e   = W_xh[(size_t)tok * RNN_H + cg];
        float arg = __fadd_rn(__fadd_rn(e, acc), bh);
        float h   = xla_tanh_t2(arg);

        __stcg(g_Hs + (size_t)t * (RNN_B * RNN_H) + b * RNN_H + cg, h);

        __threadfence();
        __syncthreads();
        if (tid == 0) {
            atomicAdd(&g_bar, 1u);
            const unsigned target = (unsigned)(t + 1) * G;
            while (*((volatile unsigned int*)&g_bar) < target) __nanosleep(64);
            __threadfence();
        }
        __syncthreads();
    }
}

// =============================================================================
// Split kernels: x -> (bf16 hi, bf16 lo) with hi = bf16(x), lo = bf16(x - hi)
// =============================================================================
__device__ __forceinline__ void split_store(const float4 v,
                                            __nv_bfloat16* hi,
                                            __nv_bfloat16* lo) {
    __nv_bfloat162 h01 = __floats2bfloat162_rn(v.x, v.y);
    __nv_bfloat162 h23 = __floats2bfloat162_rn(v.z, v.w);
    float r0 = v.x - __bfloat162float(__low2bfloat16(h01));
    float r1 = v.y - __bfloat162float(__high2bfloat16(h01));
    float r2 = v.z - __bfloat162float(__low2bfloat16(h23));
    float r3 = v.w - __bfloat162float(__high2bfloat16(h23));
    __nv_bfloat162 l01 = __floats2bfloat162_rn(r0, r1);
    __nv_bfloat162 l23 = __floats2bfloat162_rn(r2, r3);
    *(__nv_bfloat162*)(hi)     = h01;
    *(__nv_bfloat162*)(hi + 2) = h23;
    *(__nv_bfloat162*)(lo)     = l01;
    *(__nv_bfloat162*)(lo + 2) = l23;
}

__global__ void __launch_bounds__(256, 1) split_A_kernel() {
    int i = (blockIdx.x * 256 + threadIdx.x) * 4;
    if (i < TB_ROWS * RNN_H) {
        float4 v = *(const float4*)(g_Hs + i);
        split_store(v, g_Ahi + i, g_Alo + i);
    }
}
__global__ void __launch_bounds__(256, 1) split_B_kernel(const float* __restrict__ Why) {
    int i = (blockIdx.x * 256 + threadIdx.x) * 4;
    if (i < RNN_H * RNN_V) {
        float4 v = *(const float4*)(Why + i);
        split_store(v, g_Bhi + i, g_Blo + i);
    }
}

// =============================================================================
// Kernel 2: out[8192,32000] = A @ B + b_y via bf16 3-split mma.sync tensor core
// CTA 128x128, BK=32, 8 warps (2x4), warp tile 64x32, m16n8k16 fragments.
// A smem [128][40] bf16 (row-major, pad->conflict-free LDSM);
// B smem [32][136] bf16 ([k][n] row-major, ldmatrix.x2.trans).
// Double-buffered; 3 HMMA per (m,n,k16) position: AhiBhi + AhiBlo + AloBhi.
// =============================================================================
#define SA 40
#define SB 136
// bf16-unit offsets inside dynamic smem
#define AHO(b) ((b) * 5120)
#define ALO(b) (10240 + (b) * 5120)
#define BHO(b) (20480 + (b) * 4352)
#define BLO(b) (29184 + (b) * 4352)
#define GEMM_SMEM_BYTES (37888 * 2)   // 75776

__device__ __forceinline__ uint32_t cvta_sm(const void* p) {
    return (uint32_t)__cvta_generic_to_shared(p);
}
__device__ __forceinline__ void ldsm_x4(uint32_t* r, uint32_t addr) {
    asm volatile("ldmatrix.sync.aligned.m8n8.x4.shared.b16 {%0,%1,%2,%3}, [%4];"
        : "=r"(r[0]), "=r"(r[1]), "=r"(r[2]), "=r"(r[3]) : "r"(addr));
}
__device__ __forceinline__ void ldsm_x2_t(uint32_t* r, uint32_t addr) {
    asm volatile("ldmatrix.sync.aligned.m8n8.x2.trans.shared.b16 {%0,%1}, [%2];"
        : "=r"(r[0]), "=r"(r[1]) : "r"(addr));
}
__device__ __forceinline__ void hmma(float* c, const uint32_t* a, const uint32_t* b) {
    asm volatile("mma.sync.aligned.m16n8k16.row.col.f32.bf16.bf16.f32 "
        "{%0,%1,%2,%3},{%4,%5,%6,%7},{%8,%9},{%0,%1,%2,%3};"
        : "+f"(c[0]), "+f"(c[1]), "+f"(c[2]), "+f"(c[3])
        : "r"(a[0]), "r"(a[1]), "r"(a[2]), "r"(a[3]), "r"(b[0]), "r"(b[1]));
}

__global__ void __launch_bounds__(256, 1)
rnn_out_gemm_tc(const float* __restrict__ b_y, float* __restrict__ out) {
    extern __shared__ __nv_bfloat16 sm[];

    const int tid  = threadIdx.x;
    const int lane = tid & 31;
    const int wid  = tid >> 5;
    const int wm   = wid & 1;          // 0..1  (64-row slabs)
    const int wn   = wid >> 1;         // 0..3  (32-col slabs)
    const int n0   = blockIdx.x * 128;
    const int m0   = blockIdx.y * 128;

    // loader coords
    const int ar = tid >> 1;                 // A row 0..127
    const int ab = (tid & 1) * 16;           // A k-half {0,16}
    const int bk = tid >> 3;                 // B k row 0..31
    const int nb = (tid & 7) * 16;           // B n-chunk {0..112}

    // ldmatrix lane addressing
    const int lrow = lane & 15;
    const int acol = ((lane >> 4) & 1) * 8;

    float acc[4][4][4];
    #pragma unroll
    for (int i = 0; i < 4; ++i)
        #pragma unroll
        for (int j = 0; j < 4; ++j)
            #pragma unroll
            for (int k = 0; k < 4; ++k) acc[i][j][k] = 0.f;

    // ---- prologue: tile 0 into buffer 0 ----
    {
        const __nv_bfloat16* gah = g_Ahi + (size_t)(m0 + ar) * RNN_H + ab;
        const __nv_bfloat16* gal = g_Alo + (size_t)(m0 + ar) * RNN_H + ab;
        const __nv_bfloat16* gbh = g_Bhi + (size_t)bk * RNN_V + n0 + nb;
        const __nv_bfloat16* gbl = g_Blo + (size_t)bk * RNN_V + n0 + nb;
        *(uint4*)(sm + AHO(0) + ar * SA + ab)     = *(const uint4*)(gah);
        *(uint4*)(sm + AHO(0) + ar * SA + ab + 8) = *(const uint4*)(gah + 8);
        *(uint4*)(sm + ALO(0) + ar * SA + ab)     = *(const uint4*)(gal);
        *(uint4*)(sm + ALO(0) + ar * SA + ab + 8) = *(const uint4*)(gal + 8);
        *(uint4*)(sm + BHO(0) + bk * SB + nb)     = *(const uint4*)(gbh);
        *(uint4*)(sm + BHO(0) + bk * SB + nb + 8) = *(const uint4*)(gbh + 8);
        *(uint4*)(sm + BLO(0) + bk * SB + nb)     = *(const uint4*)(gbl);
        *(uint4*)(sm + BLO(0) + bk * SB + nb + 8) = *(const uint4*)(gbl + 8);
    }
    __syncthreads();

    const int NKT = RNN_H / 32;   // 16
    for (int kt = 0; kt < NKT; ++kt) {
        const int cur = kt & 1;

        // prefetch next tile to registers (hidden under MMA)
        uint4 pah0, pah1, pal0, pal1, pbh0, pbh1, pbl0, pbl1;
        if (kt < NKT - 1) {
            const int kb = (kt + 1) * 32;
            const __nv_bfloat16* gah = g_Ahi + (size_t)(m0 + ar) * RNN_H + kb + ab;
            const __nv_bfloat16* gal = g_Alo + (size_t)(m0 + ar) * RNN_H + kb + ab;
            const __nv_bfloat16* gbh = g_Bhi + (size_t)(kb + bk) * RNN_V + n0 + nb;
            const __nv_bfloat16* gbl = g_Blo + (size_t)(kb + bk) * RNN_V + n0 + nb;
            pah0 = *(const uint4*)(gah);  pah1 = *(const uint4*)(gah + 8);
            pal0 = *(const uint4*)(gal);  pal1 = *(const uint4*)(gal + 8);
            pbh0 = *(const uint4*)(gbh);  pbh1 = *(const uint4*)(gbh + 8);
            pbl0 = *(const uint4*)(gbl);  pbl1 = *(const uint4*)(gbl + 8);
        }

        // ---- compute: two k16 chunks ----
        #pragma unroll
        for (int kc = 0; kc < 2; ++kc) {
            uint32_t Ah[4][4], Al[4][4], Bh[4][2], Bl[4][2];
            #pragma unroll
            for (int fm = 0; fm < 4; ++fm) {
                int off = (wm * 64 + fm * 16 + lrow) * SA + kc * 16 + acol;
                ldsm_x4(Ah[fm], cvta_sm(sm + AHO(cur) + off));
                ldsm_x4(Al[fm], cvta_sm(sm + ALO(cur) + off));
            }
            #pragma unroll
            for (int fn = 0; fn < 4; ++fn) {
                int off = (kc * 16 + lrow) * SB + wn * 32 + fn * 8;
                ldsm_x2_t(Bh[fn], cvta_sm(sm + BHO(cur) + off));
                ldsm_x2_t(Bl[fn], cvta_sm(sm + BLO(cur) + off));
            }
            #pragma unroll
            for (int fm = 0; fm < 4; ++fm)
                #pragma unroll
                for (int fn = 0; fn < 4; ++fn) {
                    hmma(acc[fm][fn], Ah[fm], Bh[fn]);
                    hmma(acc[fm][fn], Ah[fm], Bl[fn]);
                    hmma(acc[fm][fn], Al[fm], Bh[fn]);
                }
        }

        if (kt < NKT - 1) {
            const int nxt = cur ^ 1;
            *(uint4*)(sm + AHO(nxt) + ar * SA + ab)     = pah0;
            *(uint4*)(sm + AHO(nxt) + ar * SA + ab + 8) = pah1;
            *(uint4*)(sm + ALO(nxt) + ar * SA + ab)     = pal0;
            *(uint4*)(sm + ALO(nxt) + ar * SA + ab + 8) = pal1;
            *(uint4*)(sm + BHO(nxt) + bk * SB + nb)     = pbh0;
            *(uint4*)(sm + BHO(nxt) + bk * SB + nb + 8) = pbh1;
            *(uint4*)(sm + BLO(nxt) + bk * SB + nb)     = pbl0;
            *(uint4*)(sm + BLO(nxt) + bk * SB + nb + 8) = pbl1;
            __syncthreads();
        }
    }

    // ---- epilogue: bias + store ----
    const int g   = lane >> 2;
    const int tig = lane & 3;
    #pragma unroll
    for (int fn = 0; fn < 4; ++fn) {
        const int col = n0 + wn * 32 + fn * 8 + tig * 2;
        float2 by = *(const float2*)(b_y + col);
        #pragma unroll
        for (int fm = 0; fm < 4; ++fm) {
            const int row = m0 + wm * 64 + fm * 16 + g;
            float2 v0 = make_float2(acc[fm][fn][0] + by.x, acc[fm][fn][1] + by.y);
            float2 v1 = make_float2(acc[fm][fn][2] + by.x, acc[fm][fn][3] + by.y);
            *(float2*)(out + (size_t)row * RNN_V + col)       = v0;
            *(float2*)(out + (size_t)(row + 8) * RNN_V + col) = v1;
        }
    }
}

// =============================================================================
// Kernel 3: optional H_final tail
// =============================================================================
__global__ void rnn_copy_hfinal(float* __restrict__ dst) {
    int i = blockIdx.x * 256 + threadIdx.x;
    if (i < RNN_B * RNN_H)
        dst[i] = g_Hs[(size_t)(RNN_T - 1) * (RNN_B * RNN_H) + i];
}

// =============================================================================
// launch
// =============================================================================
extern "C" void kernel_launch(void* const* d_in, const int* in_sizes, int n_in,
                              void* d_out, int out_size) {
    int ix = 0, ih0 = 1, iwxh = 2, iwhh = 3, ibh = 4, iwhy = 5, iby = 6;

    if (n_in == 7) {
        int fx = -1, fh0 = -1, fwhh = -1, fbh = -1, fby = -1, big0 = -1, big1 = -1;
        for (int i = 0; i < 7; ++i) {
            int s = in_sizes[i];
            if      (s == 8192)       fx = i;
            else if (s == 16384)      fh0 = i;
            else if (s == 262144)     fwhh = i;
            else if (s == 512)        fbh = i;
            else if (s == 32000)      fby = i;
            else if (s == 16384000) { if (big0 < 0) big0 = i; else big1 = i; }
        }
        if (fx >= 0 && fh0 >= 0 && fwhh >= 0 && fbh >= 0 && fby >= 0 &&
            big0 >= 0 && big1 >= 0) {
            ix = fx; ih0 = fh0; iwhh = fwhh; ibh = fbh; iby = fby;
            if (fx == 0) { iwxh = big0; iwhy = big1; }
            else         { iwhy = big0; iwxh = big1; }
        }
    }

    const void*  x    = d_in[ix];
    const float* H0   = (const float*)d_in[ih0];
    const float* W_xh = (const float*)d_in[iwxh];
    const float* W_hh = (const float*)d_in[iwhh];
    const float* b_h  = (const float*)d_in[ibh];
    const float* W_hy = (const float*)d_in[iwhy];
    const float* b_y  = (const float*)d_in[iby];
    float* out = (float*)d_out;

    static int smem_set = 0;
    if (!smem_set) {
        cudaFuncSetAttribute(rnn_out_gemm_tc,
                             cudaFuncAttributeMaxDynamicSharedMemorySize,
                             GEMM_SMEM_BYTES);
        smem_set = 1;
    }

    rnn_prep<<<1, 256>>>((const unsigned int*)x);
    rnn_recurrence<<<64, 256>>>(x, H0, W_xh, W_hh, b_h);

    split_A_kernel<<<(TB_ROWS * RNN_H / 4 + 255) / 256, 256>>>();
    split_B_kernel<<<(RNN_H * RNN_V / 4 + 255) / 256, 256>>>(W_hy);

    dim3 grid(RNN_V / 128, TB_ROWS / 128);   // (250, 64)
    rnn_out_gemm_tc<<<grid, 256, GEMM_SMEM_BYTES>>>(b_y, out);

    const long long main_elems = (long long)TB_ROWS * RNN_V;
    if ((long long)out_size >= main_elems + (long long)RNN_B * RNN_H)
        rnn_copy_hfinal<<<(RNN_B * RNN_H + 255) / 256, 256>>>(out + main_elems);
}

// round 16
// speedup vs baseline: 1.9482x; 1.1717x over previous
#include <cuda_runtime.h>
#include <cuda_bf16.h>
#include <cuda_fp16.h>
#include <cstdint>

// Problem constants
#define RNN_B     32
#define RNN_T     256
#define RNN_H     512
#define RNN_V     32000
#define TB_ROWS   (RNN_T * RNN_B)       // 8192

// -------------------- device scratch (no allocation allowed) ----------------
__device__ float        g_Hs[TB_ROWS * RNN_H];        // hidden states, 16 MB
__device__ int          g_x_is_i32;
__device__ unsigned int g_bar;
__device__ __half       g_Ah[TB_ROWS * RNN_H];        // A fp16 [M][K], 8 MB
__device__ __half       g_Bh[(size_t)RNN_H * RNN_V];  // B fp16 [K][N], 32 MB

// =============================================================================
// MATCHED reference arithmetic (decoded R9-R11): split-K=2 fmaf chains + T2 tanh
// =============================================================================
__device__ __forceinline__ float xla_tanh_t2(float a) {
    const float kClamp = 7.99881172180175781f;
    float x = fminf(fmaxf(a, -kClamp), kClamp);
    float x2 = __fmul_rn(x, x);
    float p = -2.76076847742355e-16f;
    p = fmaf(x2, p,  2.00018790482477e-13f);
    p = fmaf(x2, p, -8.60467152213735e-11f);
    p = fmaf(x2, p,  5.12229709037114e-08f);
    p = fmaf(x2, p,  1.48572235717979e-05f);
    p = fmaf(x2, p,  6.37261928875436e-04f);
    p = fmaf(x2, p,  4.89352455891786e-03f);
    p = __fmul_rn(x, p);
    float q = 1.19825839466702e-06f;
    q = fmaf(x2, q,  1.18534705686654e-04f);
    q = fmaf(x2, q,  2.26843463243900e-03f);
    q = fmaf(x2, q,  4.89352518554385e-03f);
    float r = __fdiv_rn(p, q);
    return (fabsf(a) < 0.0004f) ? a : r;
}

__device__ __forceinline__ float chain_seq(const float* __restrict__ h,
                                           const float* __restrict__ w,
                                           int k0, int k1) {
    float acc = 0.f;
    #pragma unroll 8
    for (int k = k0; k < k1; ++k) acc = fmaf(h[k], w[k], acc);
    return acc;
}

// =============================================================================
// Kernel 0: probe token dtype and reset grid barrier.
// =============================================================================
__global__ void __launch_bounds__(256, 1)
rnn_prep(const unsigned int* __restrict__ xw) {
    __shared__ int s_any;
    if (threadIdx.x == 0) s_any = 0;
    __syncthreads();
    int any = 0;
    for (int i = threadIdx.x; i < (RNN_B * RNN_T) / 2; i += 256)
        any |= (xw[2 * i + 1] != 0u);
    if (any) atomicOr(&s_any, 1);
    __syncthreads();
    if (threadIdx.x == 0) { g_x_is_i32 = s_any; g_bar = 0u; }
}

// =============================================================================
// Kernel 1: recurrence, bit-exact matched arithmetic. 512 threads/CTA:
// the S2 dot is exactly two independent 256-FMA chains -> paired threads
// (s = tid&1) compute p0/p1 in parallel, combined via shfl + one __fadd_rn.
// Identical bit pattern to the sequential version; chain latency halved.
// =============================================================================
__global__ void __launch_bounds__(512, 1)
rnn_recurrence(const void*  __restrict__ xraw,
               const float* __restrict__ H0,
               const float* __restrict__ W_xh,
               const float* __restrict__ W_hh,
               const float* __restrict__ b_h) {
    __shared__ float Wsm[8 * 516];
    __shared__ float Hsm[32 * 516];

    const int tid = threadIdx.x;
    const int b   = tid >> 4;          // batch row 0..31
    const int c   = (tid >> 1) & 7;    // local column 0..7
    const int s   = tid & 1;           // chain half 0/1
    const int cg  = blockIdx.x * 8 + c;

    for (int i = tid; i < 8 * 512; i += 512) {
        int jc = i >> 9, k = i & 511;
        Wsm[jc * 516 + k] = W_hh[(size_t)k * RNN_H + blockIdx.x * 8 + jc];
    }
    const float bh = b_h[cg];
    __syncthreads();

    const int        is32 = g_x_is_i32;
    const int*       x32  = (const int*)xraw;
    const long long* x64  = (const long long*)xraw;
    const float*     wrow = Wsm + c * 516;
    const float*     hrow = Hsm + b * 516;
    const unsigned   G    = gridDim.x;

    for (int t = 0; t < RNN_T; ++t) {
        const float* Hp = (t == 0) ? H0
                                   : (g_Hs + (size_t)(t - 1) * (RNN_B * RNN_H));
        for (int j = tid; j < (RNN_B * RNN_H) / 4; j += 512) {
            int br = j >> 7, k4 = j & 127;
            float4 v = __ldcg((const float4*)(Hp + (size_t)br * RNN_H + k4 * 4));
            *(float4*)(Hsm + br * 516 + k4 * 4) = v;
        }
        __syncthreads();

        // each thread: ONE 256-length sequential fmaf chain (its half)
        float pme = chain_seq(hrow, wrow, s * 256, s * 256 + 256);
        float pot = __shfl_xor_sync(0xFFFFFFFFu, pme, 1);

        if (s == 0) {
            float acc = __fadd_rn(pme, pot);   // p0 + p1, matched order
            long long tok = is32 ? (long long)x32[b * RNN_T + t]
                                 : x64[b * RNN_T + t];
            float e   = W_xh[(size_t)tok * RNN_H + cg];
            float arg = __fadd_rn(__fadd_rn(e, acc), bh);
            float h   = xla_tanh_t2(arg);
            __stcg(g_Hs + (size_t)t * (RNN_B * RNN_H) + b * RNN_H + cg, h);
        }

        __threadfence();
        __syncthreads();
        if (tid == 0) {
            atomicAdd(&g_bar, 1u);
            const unsigned target = (unsigned)(t + 1) * G;
            while (*((volatile unsigned int*)&g_bar) < target) __nanosleep(64);
            __threadfence();
        }
        __syncthreads();
    }
}

// =============================================================================
// fp16 convert kernels (single precision level: rel_err ~3e-4 << 1e-3)
// =============================================================================
__global__ void __launch_bounds__(256, 1) conv_A_kernel() {
    int i = (blockIdx.x * 256 + threadIdx.x) * 4;
    if (i < TB_ROWS * RNN_H) {
        float4 v = *(const float4*)(g_Hs + i);
        __half2 h01 = __floats2half2_rn(v.x, v.y);
        __half2 h23 = __floats2half2_rn(v.z, v.w);
        uint2 pk;
        pk.x = *(uint32_t*)&h01;
        pk.y = *(uint32_t*)&h23;
        *(uint2*)(g_Ah + i) = pk;
    }
}
__global__ void __launch_bounds__(256, 1) conv_B_kernel(const float* __restrict__ Why) {
    size_t i = ((size_t)blockIdx.x * 256 + threadIdx.x) * 4;
    if (i < (size_t)RNN_H * RNN_V) {
        float4 v = *(const float4*)(Why + i);
        __half2 h01 = __floats2half2_rn(v.x, v.y);
        __half2 h23 = __floats2half2_rn(v.z, v.w);
        uint2 pk;
        pk.x = *(uint32_t*)&h01;
        pk.y = *(uint32_t*)&h23;
        *(uint2*)(g_Bh + i) = pk;
    }
}

// =============================================================================
// Kernel 2: out[8192,32000] = A @ B + b_y, fp16 mma.sync m16n8k16, f32 acc.
// CTA 128x128, BK=64, 8 warps (2x4), warp tile 64x32.
// cp.async 2-stage pipeline; A smem stride 72 fp16 / B stride 136 fp16
// (conflict-free ldmatrix phase patterns).
// =============================================================================
#define SAH 72
#define SBH 136
// half-unit offsets in dynamic smem
#define A_OFF(bf) ((bf) * 9216)            // 128*72
#define B_OFF(bf) (18432 + (bf) * 8704)    // 64*136
#define GEMM_SMEM_BYTES ((18432 + 17408) * 2)   // 71680

__device__ __forceinline__ uint32_t sm_u32(const void* p) {
    return (uint32_t)__cvta_generic_to_shared(p);
}
__device__ __forceinline__ void cp16(uint32_t sdst, const void* gsrc) {
    asm volatile("cp.async.cg.shared.global [%0], [%1], 16;"
                 :: "r"(sdst), "l"(gsrc));
}
__device__ __forceinline__ void cp_commit() {
    asm volatile("cp.async.commit_group;" ::: "memory");
}
__device__ __forceinline__ void cp_wait0() {
    asm volatile("cp.async.wait_group 0;" ::: "memory");
}
__device__ __forceinline__ void ldsm_x4(uint32_t* r, uint32_t addr) {
    asm volatile("ldmatrix.sync.aligned.m8n8.x4.shared.b16 {%0,%1,%2,%3}, [%4];"
        : "=r"(r[0]), "=r"(r[1]), "=r"(r[2]), "=r"(r[3]) : "r"(addr));
}
__device__ __forceinline__ void ldsm_x2_t(uint32_t* r, uint32_t addr) {
    asm volatile("ldmatrix.sync.aligned.m8n8.x2.trans.shared.b16 {%0,%1}, [%2];"
        : "=r"(r[0]), "=r"(r[1]) : "r"(addr));
}
__device__ __forceinline__ void hmma16(float* c, const uint32_t* a, const uint32_t* b) {
    asm volatile("mma.sync.aligned.m16n8k16.row.col.f32.f16.f16.f32 "
        "{%0,%1,%2,%3},{%4,%5,%6,%7},{%8,%9},{%0,%1,%2,%3};"
        : "+f"(c[0]), "+f"(c[1]), "+f"(c[2]), "+f"(c[3])
        : "r"(a[0]), "r"(a[1]), "r"(a[2]), "r"(a[3]), "r"(b[0]), "r"(b[1]));
}

__global__ void __launch_bounds__(256)
rnn_out_gemm_f16(const float* __restrict__ b_y, float* __restrict__ out) {
    extern __shared__ __half sm[];

    const int tid  = threadIdx.x;
    const int lane = tid & 31;
    const int wid  = tid >> 5;
    const int wm   = wid & 1;          // 64-row slabs
    const int wn   = wid >> 1;         // 32-col slabs
    const int n0   = blockIdx.x * 128;
    const int m0   = blockIdx.y * 128;

    // loader coords
    const int arow = tid >> 1;                 // A row 0..127
    const int acb  = (tid & 1) * 4;            // A chunk base (of 8 per row)
    const int brow = tid >> 2;                 // B k-row 0..63
    const int bcb  = (tid & 3) * 4;            // B chunk base (of 16 per row)

    const int lrow = lane & 15;
    const int acol = ((lane >> 4) & 1) * 8;

    float acc[4][4][4];
    #pragma unroll
    for (int i = 0; i < 4; ++i)
        #pragma unroll
        for (int j = 0; j < 4; ++j)
            #pragma unroll
            for (int k = 0; k < 4; ++k) acc[i][j][k] = 0.f;

    // ---- async load of one stage ----
    auto load_stage = [&](int kb, int bf) {
        const __half* ga = g_Ah + (size_t)(m0 + arow) * RNN_H + kb;
        #pragma unroll
        for (int i = 0; i < 4; ++i) {
            int ch = acb + i;
            cp16(sm_u32(sm + A_OFF(bf) + arow * SAH + ch * 8), ga + ch * 8);
        }
        const __half* gb = g_Bh + (size_t)(kb + brow) * RNN_V + n0;
        #pragma unroll
        for (int i = 0; i < 4; ++i) {
            int ch = bcb + i;
            cp16(sm_u32(sm + B_OFF(bf) + brow * SBH + ch * 8), gb + ch * 8);
        }
    };

    load_stage(0, 0);
    cp_commit();

    const int NKT = RNN_H / 64;   // 8
    for (int kt = 0; kt < NKT; ++kt) {
        const int cur = kt & 1;
        cp_wait0();
        __syncthreads();
        if (kt < NKT - 1) {
            load_stage((kt + 1) * 64, cur ^ 1);
            cp_commit();
        }

        // ---- compute on buffer cur: 4 k16 chunks ----
        #pragma unroll
        for (int kc = 0; kc < 4; ++kc) {
            uint32_t Af[4][4], Bf[4][2];
            #pragma unroll
            for (int fm = 0; fm < 4; ++fm) {
                int off = (wm * 64 + fm * 16 + lrow) * SAH + kc * 16 + acol;
                ldsm_x4(Af[fm], sm_u32(sm + A_OFF(cur) + off));
            }
            #pragma unroll
            for (int fn = 0; fn < 4; ++fn) {
                int off = (kc * 16 + lrow) * SBH + wn * 32 + fn * 8;
                ldsm_x2_t(Bf[fn], sm_u32(sm + B_OFF(cur) + off));
            }
            #pragma unroll
            for (int fm = 0; fm < 4; ++fm)
                #pragma unroll
                for (int fn = 0; fn < 4; ++fn)
                    hmma16(acc[fm][fn], Af[fm], Bf[fn]);
        }
    }

    // ---- epilogue: bias + store ----
    const int g   = lane >> 2;
    const int tig = lane & 3;
    #pragma unroll
    for (int fn = 0; fn < 4; ++fn) {
        const int col = n0 + wn * 32 + fn * 8 + tig * 2;
        float2 by = *(const float2*)(b_y + col);
        #pragma unroll
        for (int fm = 0; fm < 4; ++fm) {
            const int row = m0 + wm * 64 + fm * 16 + g;
            float2 v0 = make_float2(acc[fm][fn][0] + by.x, acc[fm][fn][1] + by.y);
            float2 v1 = make_float2(acc[fm][fn][2] + by.x, acc[fm][fn][3] + by.y);
            *(float2*)(out + (size_t)row * RNN_V + col)       = v0;
            *(float2*)(out + (size_t)(row + 8) * RNN_V + col) = v1;
        }
    }
}

// =============================================================================
// Kernel 3: optional H_final tail
// =============================================================================
__global__ void rnn_copy_hfinal(float* __restrict__ dst) {
    int i = blockIdx.x * 256 + threadIdx.x;
    if (i < RNN_B * RNN_H)
        dst[i] = g_Hs[(size_t)(RNN_T - 1) * (RNN_B * RNN_H) + i];
}

// =============================================================================
// launch
// =============================================================================
extern "C" void kernel_launch(void* const* d_in, const int* in_sizes, int n_in,
                              void* d_out, int out_size) {
    int ix = 0, ih0 = 1, iwxh = 2, iwhh = 3, ibh = 4, iwhy = 5, iby = 6;

    if (n_in == 7) {
        int fx = -1, fh0 = -1, fwhh = -1, fbh = -1, fby = -1, big0 = -1, big1 = -1;
        for (int i = 0; i < 7; ++i) {
            int s = in_sizes[i];
            if      (s == 8192)       fx = i;
            else if (s == 16384)      fh0 = i;
            else if (s == 262144)     fwhh = i;
            else if (s == 512)        fbh = i;
            else if (s == 32000)      fby = i;
            else if (s == 16384000) { if (big0 < 0) big0 = i; else big1 = i; }
        }
        if (fx >= 0 && fh0 >= 0 && fwhh >= 0 && fbh >= 0 && fby >= 0 &&
            big0 >= 0 && big1 >= 0) {
            ix = fx; ih0 = fh0; iwhh = fwhh; ibh = fbh; iby = fby;
            if (fx == 0) { iwxh = big0; iwhy = big1; }
            else         { iwhy = big0; iwxh = big1; }
        }
    }

    const void*  x    = d_in[ix];
    const float* H0   = (const float*)d_in[ih0];
    const float* W_xh = (const float*)d_in[iwxh];
    const float* W_hh = (const float*)d_in[iwhh];
    const float* b_h  = (const float*)d_in[ibh];
    const float* W_hy = (const float*)d_in[iwhy];
    const float* b_y  = (const float*)d_in[iby];
    float* out = (float*)d_out;

    static int smem_set = 0;
    if (!smem_set) {
        cudaFuncSetAttribute(rnn_out_gemm_f16,
                             cudaFuncAttributeMaxDynamicSharedMemorySize,
                             GEMM_SMEM_BYTES);
        smem_set = 1;
    }

    rnn_prep<<<1, 256>>>((const unsigned int*)x);
    rnn_recurrence<<<64, 512>>>(x, H0, W_xh, W_hh, b_h);

    conv_A_kernel<<<(TB_ROWS * RNN_H / 4 + 255) / 256, 256>>>();
    conv_B_kernel<<<(int)(((size_t)RNN_H * RNN_V / 4 + 255) / 256), 256>>>(W_hy);

    dim3 grid(RNN_V / 128, TB_ROWS / 128);   // (250, 64)
    rnn_out_gemm_f16<<<grid, 256, GEMM_SMEM_BYTES>>>(b_y, out);

    const long long main_elems = (long long)TB_ROWS * RNN_V;
    if ((long long)out_size >= main_elems + (long long)RNN_B * RNN_H)
        rnn_copy_hfinal<<<(RNN_B * RNN_H + 255) / 256, 256>>>(out + main_elems);
}

// round 17
// speedup vs baseline: 2.5363x; 1.3019x over previous
#include <cuda_runtime.h>
#include <cuda_bf16.h>
#include <cuda_fp16.h>
#include <cstdint>

// Problem constants
#define RNN_B     32
#define RNN_T     256
#define RNN_H     512
#define RNN_V     32000
#define TB_ROWS   (RNN_T * RNN_B)       // 8192

// -------------------- device scratch (no allocation allowed) ----------------
__device__ float        g_Hs[TB_ROWS * RNN_H];        // hidden states, 16 MB
__device__ int          g_x_is_i32;
__device__ unsigned int g_bar;
__device__ __half       g_Ah[TB_ROWS * RNN_H];        // A fp16 [M][K], 8 MB
__device__ __half       g_Bh[(size_t)RNN_H * RNN_V];  // B fp16 [K][N], 32 MB

// =============================================================================
// MATCHED reference arithmetic (decoded R9-R11): split-K=2 fmaf chains + T2 tanh
// =============================================================================
__device__ __forceinline__ float xla_tanh_t2(float a) {
    const float kClamp = 7.99881172180175781f;
    float x = fminf(fmaxf(a, -kClamp), kClamp);
    float x2 = __fmul_rn(x, x);
    float p = -2.76076847742355e-16f;
    p = fmaf(x2, p,  2.00018790482477e-13f);
    p = fmaf(x2, p, -8.60467152213735e-11f);
    p = fmaf(x2, p,  5.12229709037114e-08f);
    p = fmaf(x2, p,  1.48572235717979e-05f);
    p = fmaf(x2, p,  6.37261928875436e-04f);
    p = fmaf(x2, p,  4.89352455891786e-03f);
    p = __fmul_rn(x, p);
    float q = 1.19825839466702e-06f;
    q = fmaf(x2, q,  1.18534705686654e-04f);
    q = fmaf(x2, q,  2.26843463243900e-03f);
    q = fmaf(x2, q,  4.89352518554385e-03f);
    float r = __fdiv_rn(p, q);
    return (fabsf(a) < 0.0004f) ? a : r;
}

// =============================================================================
// Kernel 0: probe token dtype and reset grid barrier.
// =============================================================================
__global__ void __launch_bounds__(256, 1)
rnn_prep(const unsigned int* __restrict__ xw) {
    __shared__ int s_any;
    if (threadIdx.x == 0) s_any = 0;
    __syncthreads();
    int any = 0;
    for (int i = threadIdx.x; i < (RNN_B * RNN_T) / 2; i += 256)
        any |= (xw[2 * i + 1] != 0u);
    if (any) atomicOr(&s_any, 1);
    __syncthreads();
    if (threadIdx.x == 0) { g_x_is_i32 = s_any; g_bar = 0u; }
}

// =============================================================================
// Kernel 1: recurrence, bit-exact matched arithmetic (S2 x T2), smem-optimized.
// 128 CTAs x 256 threads (all co-resident). CTA owns 4 H columns.
// Warp = one column c, 16 batches x 2 chain-halves:
//   lane: b = bg*16 + (lane>>1), s = lane&1.
//   w reads: same column -> <=2 distinct addrs per LDS.128 (near-broadcast).
//   h reads: layout f4 = b*130 + s*65 + k4 -> (2b+s) mod 8 distinct per phase
//            => conflict-free 4-phase LDS.128.
// Chain arithmetic identical to the matched reference: two ascending 256-fmaf
// chains, combined with one __fadd_rn (halves paired in-warp, shfl_xor 1).
// =============================================================================
__global__ void __launch_bounds__(256, 1)
rnn_recurrence(const void*  __restrict__ xraw,
               const float* __restrict__ H0,
               const float* __restrict__ W_xh,
               const float* __restrict__ W_hh,
               const float* __restrict__ b_h) {
    __shared__ float  Wsm[4 * 520];        // 4 columns, f4-aligned stride
    __shared__ float4 Hsm4[32 * 130];      // b*130 + s*65 + k4

    const int tid  = threadIdx.x;
    const int lane = tid & 31;
    const int w    = tid >> 5;             // 8 warps
    const int c    = w >> 1;               // column 0..3
    const int bg   = w & 1;                // batch group
    const int b    = bg * 16 + (lane >> 1);
    const int s    = lane & 1;             // chain half
    const int cg   = blockIdx.x * 4 + c;

    for (int i = tid; i < 4 * 512; i += 256) {
        int jc = i >> 9, k = i & 511;
        Wsm[jc * 520 + k] = W_hh[(size_t)k * RNN_H + blockIdx.x * 4 + jc];
    }
    const float bh = b_h[cg];
    __syncthreads();

    const int        is32 = g_x_is_i32;
    const int*       x32  = (const int*)xraw;
    const long long* x64  = (const long long*)xraw;
    const float*     wrow = Wsm + c * 520 + s * 256;
    const float4*    hbase = Hsm4 + b * 130 + s * 65;
    const unsigned   G    = gridDim.x;

    for (int t = 0; t < RNN_T; ++t) {
        // ---- cooperative stage of H_prev (32x512) into banked layout ----
        const float* Hp = (t == 0) ? H0
                                   : (g_Hs + (size_t)(t - 1) * (RNN_B * RNN_H));
        for (int j = tid; j < 4096; j += 256) {
            int br = j >> 7, k7 = j & 127;
            Hsm4[br * 130 + (k7 >> 6) * 65 + (k7 & 63)] =
                __ldcg((const float4*)(Hp + (size_t)br * RNN_H + k7 * 4));
        }
        __syncthreads();

        // ---- one 256-length ascending fmaf chain (this lane's half) ----
        float acc = 0.f;
        #pragma unroll 8
        for (int k4 = 0; k4 < 64; ++k4) {
            float4 h  = hbase[k4];
            float4 wv = *(const float4*)(wrow + k4 * 4);
            acc = fmaf(h.x, wv.x, acc);
            acc = fmaf(h.y, wv.y, acc);
            acc = fmaf(h.z, wv.z, acc);
            acc = fmaf(h.w, wv.w, acc);
        }
        float pot = __shfl_xor_sync(0xFFFFFFFFu, acc, 1);

        if (s == 0) {
            float sum = __fadd_rn(acc, pot);     // p0 + p1, matched order
            long long tok = is32 ? (long long)x32[b * RNN_T + t]
                                 : x64[b * RNN_T + t];
            float e   = W_xh[(size_t)tok * RNN_H + cg];
            float arg = __fadd_rn(__fadd_rn(e, sum), bh);
            float h   = xla_tanh_t2(arg);
            __stcg(g_Hs + (size_t)t * (RNN_B * RNN_H) + b * RNN_H + cg, h);
        }

        __threadfence();
        __syncthreads();
        if (tid == 0) {
            atomicAdd(&g_bar, 1u);
            const unsigned target = (unsigned)(t + 1) * G;
            while (*((volatile unsigned int*)&g_bar) < target) __nanosleep(64);
            __threadfence();
        }
        __syncthreads();
    }
}

// =============================================================================
// fp16 convert kernels
// =============================================================================
__global__ void __launch_bounds__(256, 1) conv_A_kernel() {
    int i = (blockIdx.x * 256 + threadIdx.x) * 4;
    if (i < TB_ROWS * RNN_H) {
        float4 v = *(const float4*)(g_Hs + i);
        __half2 h01 = __floats2half2_rn(v.x, v.y);
        __half2 h23 = __floats2half2_rn(v.z, v.w);
        uint2 pk;
        pk.x = *(uint32_t*)&h01;
        pk.y = *(uint32_t*)&h23;
        *(uint2*)(g_Ah + i) = pk;
    }
}
__global__ void __launch_bounds__(256, 1) conv_B_kernel(const float* __restrict__ Why) {
    size_t i = ((size_t)blockIdx.x * 256 + threadIdx.x) * 4;
    if (i < (size_t)RNN_H * RNN_V) {
        float4 v = *(const float4*)(Why + i);
        __half2 h01 = __floats2half2_rn(v.x, v.y);
        __half2 h23 = __floats2half2_rn(v.z, v.w);
        uint2 pk;
        pk.x = *(uint32_t*)&h01;
        pk.y = *(uint32_t*)&h23;
        *(uint2*)(g_Bh + i) = pk;
    }
}

// =============================================================================
// Kernel 2: out[8192,32000] = A @ B + b_y, fp16 mma.sync m16n8k16, f32 acc.
// CTA 256x128, BK=64, 512 threads = 16 warps (4x4), warp tile 64x32.
// cp.async 2-stage pipeline; A stride 72 / B stride 136 (conflict-free ldsm).
// 25% less L2 traffic than 128x128 and 2x compute per pipeline stage.
// =============================================================================
#define SAH 72
#define SBH 136
#define A_OFF(bf) ((bf) * 18432)            // 256*72 halves
#define B_OFF(bf) (36864 + (bf) * 8704)     // 64*136 halves
#define GEMM_SMEM_BYTES ((18432 + 8704) * 2 * 2)   // 108544

__device__ __forceinline__ uint32_t sm_u32(const void* p) {
    return (uint32_t)__cvta_generic_to_shared(p);
}
__device__ __forceinline__ void cp16(uint32_t sdst, const void* gsrc) {
    asm volatile("cp.async.cg.shared.global [%0], [%1], 16;"
                 :: "r"(sdst), "l"(gsrc));
}
__device__ __forceinline__ void cp_commit() {
    asm volatile("cp.async.commit_group;" ::: "memory");
}
__device__ __forceinline__ void cp_wait0() {
    asm volatile("cp.async.wait_group 0;" ::: "memory");
}
__device__ __forceinline__ void ldsm_x4(uint32_t* r, uint32_t addr) {
    asm volatile("ldmatrix.sync.aligned.m8n8.x4.shared.b16 {%0,%1,%2,%3}, [%4];"
        : "=r"(r[0]), "=r"(r[1]), "=r"(r[2]), "=r"(r[3]) : "r"(addr));
}
__device__ __forceinline__ void ldsm_x2_t(uint32_t* r, uint32_t addr) {
    asm volatile("ldmatrix.sync.aligned.m8n8.x2.trans.shared.b16 {%0,%1}, [%2];"
        : "=r"(r[0]), "=r"(r[1]) : "r"(addr));
}
__device__ __forceinline__ void hmma16(float* c, const uint32_t* a, const uint32_t* b) {
    asm volatile("mma.sync.aligned.m16n8k16.row.col.f32.f16.f16.f32 "
        "{%0,%1,%2,%3},{%4,%5,%6,%7},{%8,%9},{%0,%1,%2,%3};"
        : "+f"(c[0]), "+f"(c[1]), "+f"(c[2]), "+f"(c[3])
        : "r"(a[0]), "r"(a[1]), "r"(a[2]), "r"(a[3]), "r"(b[0]), "r"(b[1]));
}

__global__ void __launch_bounds__(512, 1)
rnn_out_gemm_f16(const float* __restrict__ b_y, float* __restrict__ out) {
    extern __shared__ __half sm[];

    const int tid  = threadIdx.x;
    const int lane = tid & 31;
    const int wid  = tid >> 5;
    const int wm   = wid & 3;          // 64-row slabs (4)
    const int wn   = wid >> 2;         // 32-col slabs (4)
    const int n0   = blockIdx.x * 128;
    const int m0   = blockIdx.y * 256;

    // loader coords
    const int arow = tid >> 1;                 // A row 0..255
    const int acb  = (tid & 1) * 4;            // A chunk base (8 per row)
    const int brow = tid >> 3;                 // B k-row 0..63
    const int bcb  = (tid & 7) * 2;            // B chunk base (16 per row)

    const int lrow = lane & 15;
    const int acol = ((lane >> 4) & 1) * 8;

    float acc[4][4][4];
    #pragma unroll
    for (int i = 0; i < 4; ++i)
        #pragma unroll
        for (int j = 0; j < 4; ++j)
            #pragma unroll
            for (int k = 0; k < 4; ++k) acc[i][j][k] = 0.f;

    auto load_stage = [&](int kb, int bf) {
        const __half* ga = g_Ah + (size_t)(m0 + arow) * RNN_H + kb;
        #pragma unroll
        for (int i = 0; i < 4; ++i) {
            int ch = acb + i;
            cp16(sm_u32(sm + A_OFF(bf) + arow * SAH + ch * 8), ga + ch * 8);
        }
        const __half* gb = g_Bh + (size_t)(kb + brow) * RNN_V + n0;
        #pragma unroll
        for (int i = 0; i < 2; ++i) {
            int ch = bcb + i;
            cp16(sm_u32(sm + B_OFF(bf) + brow * SBH + ch * 8), gb + ch * 8);
        }
    };

    load_stage(0, 0);
    cp_commit();

    const int NKT = RNN_H / 64;   // 8
    for (int kt = 0; kt < NKT; ++kt) {
        const int cur = kt & 1;
        cp_wait0();
        __syncthreads();
        if (kt < NKT - 1) {
            load_stage((kt + 1) * 64, cur ^ 1);
            cp_commit();
        }

        #pragma unroll
        for (int kc = 0; kc < 4; ++kc) {
            uint32_t Af[4][4], Bf[4][2];
            #pragma unroll
            for (int fm = 0; fm < 4; ++fm) {
                int off = (wm * 64 + fm * 16 + lrow) * SAH + kc * 16 + acol;
                ldsm_x4(Af[fm], sm_u32(sm + A_OFF(cur) + off));
            }
            #pragma unroll
            for (int fn = 0; fn < 4; ++fn) {
                int off = (kc * 16 + lrow) * SBH + wn * 32 + fn * 8;
                ldsm_x2_t(Bf[fn], sm_u32(sm + B_OFF(cur) + off));
            }
            #pragma unroll
            for (int fm = 0; fm < 4; ++fm)
                #pragma unroll
                for (int fn = 0; fn < 4; ++fn)
                    hmma16(acc[fm][fn], Af[fm], Bf[fn]);
        }
    }

    // ---- epilogue: bias + store ----
    const int g   = lane >> 2;
    const int tig = lane & 3;
    #pragma unroll
    for (int fn = 0; fn < 4; ++fn) {
        const int col = n0 + wn * 32 + fn * 8 + tig * 2;
        float2 by = *(const float2*)(b_y + col);
        #pragma unroll
        for (int fm = 0; fm < 4; ++fm) {
            const int row = m0 + wm * 64 + fm * 16 + g;
            float2 v0 = make_float2(acc[fm][fn][0] + by.x, acc[fm][fn][1] + by.y);
            float2 v1 = make_float2(acc[fm][fn][2] + by.x, acc[fm][fn][3] + by.y);
            *(float2*)(out + (size_t)row * RNN_V + col)       = v0;
            *(float2*)(out + (size_t)(row + 8) * RNN_V + col) = v1;
        }
    }
}

// =============================================================================
// Kernel 3: optional H_final tail
// =============================================================================
__global__ void rnn_copy_hfinal(float* __restrict__ dst) {
    int i = blockIdx.x * 256 + threadIdx.x;
    if (i < RNN_B * RNN_H)
        dst[i] = g_Hs[(size_t)(RNN_T - 1) * (RNN_B * RNN_H) + i];
}

// =============================================================================
// launch
// =============================================================================
extern "C" void kernel_launch(void* const* d_in, const int* in_sizes, int n_in,
                              void* d_out, int out_size) {
    int ix = 0, ih0 = 1, iwxh = 2, iwhh = 3, ibh = 4, iwhy = 5, iby = 6;

    if (n_in == 7) {
        int fx = -1, fh0 = -1, fwhh = -1, fbh = -1, fby = -1, big0 = -1, big1 = -1;
        for (int i = 0; i < 7; ++i) {
            int s = in_sizes[i];
            if      (s == 8192)       fx = i;
            else if (s == 16384)      fh0 = i;
            else if (s == 262144)     fwhh = i;
            else if (s == 512)        fbh = i;
            else if (s == 32000)      fby = i;
            else if (s == 16384000) { if (big0 < 0) big0 = i; else big1 = i; }
        }
        if (fx >= 0 && fh0 >= 0 && fwhh >= 0 && fbh >= 0 && fby >= 0 &&
            big0 >= 0 && big1 >= 0) {
            ix = fx; ih0 = fh0; iwhh = fwhh; ibh = fbh; iby = fby;
            if (fx == 0) { iwxh = big0; iwhy = big1; }
            else         { iwhy = big0; iwxh = big1; }
        }
    }

    const void*  x    = d_in[ix];
    const float* H0   = (const float*)d_in[ih0];
    const float* W_xh = (const float*)d_in[iwxh];
    const float* W_hh = (const float*)d_in[iwhh];
    const float* b_h  = (const float*)d_in[ibh];
    const float* W_hy = (const float*)d_in[iwhy];
    const float* b_y  = (const float*)d_in[iby];
    float* out = (float*)d_out;

    static int smem_set = 0;
    if (!smem_set) {
        cudaFuncSetAttribute(rnn_out_gemm_f16,
                             cudaFuncAttributeMaxDynamicSharedMemorySize,
                             GEMM_SMEM_BYTES);
        smem_set = 1;
    }

    rnn_prep<<<1, 256>>>((const unsigned int*)x);
    rnn_recurrence<<<128, 256>>>(x, H0, W_xh, W_hh, b_h);

    conv_A_kernel<<<(TB_ROWS * RNN_H / 4 + 255) / 256, 256>>>();
    conv_B_kernel<<<(int)(((size_t)RNN_H * RNN_V / 4 + 255) / 256), 256>>>(W_hy);

    dim3 grid(RNN_V / 128, TB_ROWS / 256);   // (250, 32)
    rnn_out_gemm_f16<<<grid, 512, GEMM_SMEM_BYTES>>>(b_y, out);

    const long long main_elems = (long long)TB_ROWS * RNN_V;
    if ((long long)out_size >= main_elems + (long long)RNN_B * RNN_H)
        rnn_copy_hfinal<<<(RNN_B * RNN_H + 255) / 256, 256>>>(out + main_elems);
}